// round 2
// baseline (speedup 1.0000x reference)
#include <cuda_runtime.h>

// PatchIoULoss: anchor loops in the reference run exactly once (B=16<64, C=1<64).
// Computation: per batch b over the top-left 64x64 patch of a (16,1,1024,1024) image:
//   iand_b = sum(pred*target), ior_b = sum(pred)+sum(target)-iand_b
//   out = sum_b (1 - iand_b/ior_b)
//
// R1 post-mortem: 16-block version was L1tex-wavefront bound on 16 SMs (5.98us).
// R2: 128 blocks (8 per batch, 8 rows each) -> one wave, 8x less traffic per SM.
// Single kernel node; last-arriving block does the deterministic final reduce.

#define BATCH 16
#define WIMG  1024
#define BLOCKS_PER_BATCH 8
#define GRID  (BATCH * BLOCKS_PER_BATCH)   // 128
#define NTHREADS 128

__device__ float        g_pi[GRID];   // partial iand
__device__ float        g_pp[GRID];   // partial sum pred
__device__ float        g_pt[GRID];   // partial sum target
__device__ unsigned int g_count = 0;

__global__ void __launch_bounds__(NTHREADS, 1)
patch_iou_kernel(const float* __restrict__ pred,
                 const float* __restrict__ target,
                 float* __restrict__ out)
{
    const int bid = blockIdx.x;
    const int b     = bid >> 3;        // batch index
    const int chunk = bid & 7;         // row-chunk within patch (8 rows each)
    const int tid = threadIdx.x;

    // Base of this batch's image, offset to this chunk's first row.
    const float4* __restrict__ p = reinterpret_cast<const float4*>(
        pred   + (size_t)b * WIMG * WIMG + (size_t)chunk * 8 * WIMG);
    const float4* __restrict__ t = reinterpret_cast<const float4*>(
        target + (size_t)b * WIMG * WIMG + (size_t)chunk * 8 * WIMG);

    // 8 rows x 16 float4 per row = 128 float4 per tensor -> 1 per thread.
    const int row = tid >> 4;          // 0..7
    const int c4  = tid & 15;          // 0..15
    const float4 pv = p[row * (WIMG / 4) + c4];
    const float4 tv = t[row * (WIMG / 4) + c4];

    float iand = pv.x * tv.x + pv.y * tv.y + pv.z * tv.z + pv.w * tv.w;
    float sp   = pv.x + pv.y + pv.z + pv.w;
    float st   = tv.x + tv.y + tv.z + tv.w;

#pragma unroll
    for (int o = 16; o > 0; o >>= 1) {
        iand += __shfl_down_sync(0xffffffffu, iand, o);
        sp   += __shfl_down_sync(0xffffffffu, sp,   o);
        st   += __shfl_down_sync(0xffffffffu, st,   o);
    }

    __shared__ float s_i[4], s_p[4], s_t[4];
    __shared__ bool  s_last;
    const int w = tid >> 5, l = tid & 31;
    if (l == 0) { s_i[w] = iand; s_p[w] = sp; s_t[w] = st; }
    __syncthreads();

    if (tid == 0) {
        float I = s_i[0] + s_i[1] + s_i[2] + s_i[3];
        float P = s_p[0] + s_p[1] + s_p[2] + s_p[3];
        float T = s_t[0] + s_t[1] + s_t[2] + s_t[3];
        g_pi[bid] = I;
        g_pp[bid] = P;
        g_pt[bid] = T;
        __threadfence();
        const unsigned int ticket = atomicAdd(&g_count, 1u);
        s_last = (ticket == GRID - 1);
    }
    __syncthreads();

    if (s_last) {
        // Deterministic final reduce: threads 0..15 each own one batch,
        // summing its 8 partials in fixed order.
        float loss = 0.0f;
        if (tid < BATCH) {
            volatile float* vi = g_pi;
            volatile float* vp = g_pp;
            volatile float* vt = g_pt;
            float I = 0.0f, P = 0.0f, T = 0.0f;
#pragma unroll
            for (int c = 0; c < BLOCKS_PER_BATCH; ++c) {
                const int idx = tid * BLOCKS_PER_BATCH + c;
                I += vi[idx];
                P += vp[idx];
                T += vt[idx];
            }
            loss = 1.0f - I / (P + T - I);
        }
        // Reduce 16 lane values within warp 0 (fixed order tree).
#pragma unroll
        for (int o = 8; o > 0; o >>= 1)
            loss += __shfl_down_sync(0xffffffffu, loss, o);
        if (tid == 0) {
            *out = loss;
            g_count = 0;   // reset for next graph replay
        }
    }
}

extern "C" void kernel_launch(void* const* d_in, const int* in_sizes, int n_in,
                              void* d_out, int out_size)
{
    const float* pred   = (const float*)d_in[0];
    const float* target = (const float*)d_in[1];
    float* out          = (float*)d_out;
    patch_iou_kernel<<<GRID, NTHREADS>>>(pred, target, out);
}

// round 3
// speedup vs baseline: 1.1262x; 1.1262x over previous
#include <cuda_runtime.h>

// PatchIoULoss: reference's anchor loops run exactly once (B=16<64, C=1<64).
// Per batch b over the top-left 64x64 patch of (16,1,1024,1024) f32 images:
//   iand_b = sum(pred*target), ior_b = sum(pred)+sum(target)-iand_b
//   out = sum_b (1 - iand_b/ior_b)
//
// R2 post-mortem: duration invariant to grid shape => latency-chain bound.
// R3: single-atomic finalize. Each block adds (loss/32 + 1.0) to a double
// accumulator; the atomic return value lets the 16th block detect it is last
// (old >= 15) AND recover the total sum -- no fence, no ticket, no re-read.

#define BATCH 16
#define WIMG  1024
#define NT    256

__device__ double g_acc = 0.0;   // packs count (integer part) + sum(loss)/32 (fraction)

__global__ void __launch_bounds__(NT, 1)
patch_iou_kernel(const float* __restrict__ pred,
                 const float* __restrict__ target,
                 float* __restrict__ out)
{
    const int b   = blockIdx.x;
    const int tid = threadIdx.x;

    const float4* __restrict__ p =
        reinterpret_cast<const float4*>(pred   + (size_t)b * WIMG * WIMG);
    const float4* __restrict__ t =
        reinterpret_cast<const float4*>(target + (size_t)b * WIMG * WIMG);

    // Patch = 64 rows x 16 float4/row (row stride 256 float4).
    // Front-batch all 8 loads for max MLP (single DRAM round trip).
    float4 pv[4], tv[4];
#pragma unroll
    for (int k = 0; k < 4; ++k) {
        const int f   = tid + k * NT;     // 0..1023
        const int idx = ((f >> 4) << 8) | (f & 15);  // row*256 + c4
        pv[k] = p[idx];
        tv[k] = t[idx];
    }

    float iand = 0.0f, sp = 0.0f, st = 0.0f;
#pragma unroll
    for (int k = 0; k < 4; ++k) {
        iand = fmaf(pv[k].x, tv[k].x, iand);
        iand = fmaf(pv[k].y, tv[k].y, iand);
        iand = fmaf(pv[k].z, tv[k].z, iand);
        iand = fmaf(pv[k].w, tv[k].w, iand);
        sp  += (pv[k].x + pv[k].y) + (pv[k].z + pv[k].w);
        st  += (tv[k].x + tv[k].y) + (tv[k].z + tv[k].w);
    }

    // Warp tree (3 independent shuffle chains pipeline per round).
#pragma unroll
    for (int o = 16; o > 0; o >>= 1) {
        iand += __shfl_down_sync(0xffffffffu, iand, o);
        sp   += __shfl_down_sync(0xffffffffu, sp,   o);
        st   += __shfl_down_sync(0xffffffffu, st,   o);
    }

    __shared__ float s_i[8], s_p[8], s_t[8];
    const int w = tid >> 5, l = tid & 31;
    if (l == 0) { s_i[w] = iand; s_p[w] = sp; s_t[w] = st; }
    __syncthreads();

    if (tid == 0) {
        float I = 0.0f, P = 0.0f, T = 0.0f;
#pragma unroll
        for (int i = 0; i < 8; ++i) { I += s_i[i]; P += s_p[i]; T += s_t[i]; }
        const float loss = 1.0f - __fdividef(I, (P + T) - I);

        // loss in (0,1); sum over <=16 blocks of loss/32 stays in (0,0.5),
        // so the integer part of g_acc is exactly the arrival count.
        const double term = (double)loss * (1.0 / 32.0) + 1.0;
        const double old  = atomicAdd(&g_acc, term);
        if (old > 14.75) {                      // I'm the 16th arriver
            *out = (float)((old + term - 16.0) * 32.0);
            g_acc = 0.0;                        // reset for next graph replay
        }
    }
}

extern "C" void kernel_launch(void* const* d_in, const int* in_sizes, int n_in,
                              void* d_out, int out_size)
{
    const float* pred   = (const float*)d_in[0];
    const float* target = (const float*)d_in[1];
    float* out          = (float*)d_out;
    patch_iou_kernel<<<BATCH, NT>>>(pred, target, out);
}